// round 2
// baseline (speedup 1.0000x reference)
#include <cuda_runtime.h>
#include <cuda_bf16.h>
#include <cstdint>

#define SEQ    8192
#define D_IN   4096
#define D_OUT  4096
#define RANK   16

// Scratch for per-token LoRA-A projection: a_out[s][r] = (x[s]·A[e_s][r]) * scaling[s]
__device__ float g_aout[SEQ * RANK];

// ---------------------------------------------------------------------------
// Kernel 1: a_out = (x @ A[e]^T) * scaling   (one block per token, 128 thr)
// ---------------------------------------------------------------------------
__global__ void lora_a_kernel(const float* __restrict__ x,
                              const float* __restrict__ A,
                              const float* __restrict__ scalings,
                              const int*   __restrict__ tok)
{
    const int s = blockIdx.x;
    const int t = threadIdx.x;                 // 128 threads
    const int e = tok[s];
    const float* xr = x + (size_t)s * D_IN;
    const float* Ae = A + (size_t)e * RANK * D_IN;

    float acc[RANK];
#pragma unroll
    for (int r = 0; r < RANK; ++r) acc[r] = 0.f;

#pragma unroll
    for (int it = 0; it < D_IN / (128 * 4); ++it) {
        const int k = t * 4 + it * 512;
        const float4 xv = *(const float4*)(xr + k);
#pragma unroll
        for (int r = 0; r < RANK; ++r) {
            const float4 av = *(const float4*)(Ae + r * D_IN + k);
            acc[r] += xv.x * av.x + xv.y * av.y + xv.z * av.z + xv.w * av.w;
        }
    }
#pragma unroll
    for (int r = 0; r < RANK; ++r) {
#pragma unroll
        for (int o = 16; o > 0; o >>= 1)
            acc[r] += __shfl_xor_sync(0xffffffffu, acc[r], o);
    }
    __shared__ float red[4][RANK];
    const int warp = t >> 5, lane = t & 31;
    if (lane == 0) {
#pragma unroll
        for (int r = 0; r < RANK; ++r) red[warp][r] = acc[r];
    }
    __syncthreads();
    if (t < RANK) {
        const float v = red[0][t] + red[1][t] + red[2][t] + red[3][t];
        g_aout[s * RANK + t] = v * scalings[s];
    }
}

// ---------------------------------------------------------------------------
// Kernel 2: out = x @ W + bias + a_out @ B[e]^T   (fused epilogue)
// 128x128 tile, BK=8, 256 threads, 8x8 per thread via packed f32x2 FMA.
// ---------------------------------------------------------------------------
#define BM 128
#define BN 128
#define BK 8

__device__ __forceinline__ void fma2(unsigned long long& d,
                                     unsigned long long a,
                                     unsigned long long b) {
    asm("fma.rn.f32x2 %0, %1, %2, %0;" : "+l"(d) : "l"(a), "l"(b));
}
__device__ __forceinline__ unsigned long long bcast2(float x) {
    unsigned long long r;
    const unsigned int u = __float_as_uint(x);
    asm("mov.b64 %0, {%1, %1};" : "=l"(r) : "r"(u));
    return r;
}
__device__ __forceinline__ float2 unpack2(unsigned long long v) {
    float2 f;
    asm("mov.b64 {%0, %1}, %2;" : "=f"(f.x), "=f"(f.y) : "l"(v));
    return f;
}

__global__ __launch_bounds__(256, 2)
void fused_gemm_kernel(const float* __restrict__ X,
                       const float* __restrict__ W,
                       const float* __restrict__ bias,
                       const float* __restrict__ Bbuf,
                       const int*   __restrict__ tok,
                       float*       __restrict__ out)
{
    __shared__ __align__(16) float As[BK][BM];
    __shared__ __align__(16) float Bs[BK][BN];
    __shared__ __align__(16) float aS[BM][RANK];
    __shared__ float biasS[BN];
    __shared__ int   eS[BM];

    const int bn = blockIdx.x, bm = blockIdx.y;
    const int t  = threadIdx.x;
    const int tx = t & 15, ty = t >> 4;

    const float* Xb = X + (size_t)(bm * BM) * D_IN;
    const float* Wb = W + bn * BN;

    const int arow = t >> 1;          // 0..127
    const int acol = (t & 1) * 4;     // 0 or 4
    const int brow = t >> 5;          // 0..7
    const int bcol = (t & 31) * 4;    // 0..124

    unsigned long long acc2[8][4];
#pragma unroll
    for (int i = 0; i < 8; ++i)
#pragma unroll
        for (int j = 0; j < 4; ++j) acc2[i][j] = 0ull;

    for (int k0 = 0; k0 < D_IN; k0 += BK) {
        const float4 av = *(const float4*)(Xb + (size_t)arow * D_IN + k0 + acol);
        const float4 bv = *(const float4*)(Wb + (size_t)(k0 + brow) * D_OUT + bcol);
        __syncthreads();
        As[acol + 0][arow] = av.x;
        As[acol + 1][arow] = av.y;
        As[acol + 2][arow] = av.z;
        As[acol + 3][arow] = av.w;
        *(float4*)&Bs[brow][bcol] = bv;
        __syncthreads();
#pragma unroll
        for (int k = 0; k < BK; ++k) {
            const float4 a0 = *(const float4*)&As[k][ty * 4];
            const float4 a1 = *(const float4*)&As[k][ty * 4 + 64];
            const ulonglong2 bq0 = *(const ulonglong2*)&Bs[k][tx * 4];
            const ulonglong2 bq1 = *(const ulonglong2*)&Bs[k][tx * 4 + 64];
            const unsigned long long b0 = bq0.x, b1 = bq0.y, b2 = bq1.x, b3 = bq1.y;
            const float ar[8] = {a0.x, a0.y, a0.z, a0.w, a1.x, a1.y, a1.z, a1.w};
#pragma unroll
            for (int i = 0; i < 8; ++i) {
                const unsigned long long ap = bcast2(ar[i]);
                fma2(acc2[i][0], ap, b0);
                fma2(acc2[i][1], ap, b1);
                fma2(acc2[i][2], ap, b2);
                fma2(acc2[i][3], ap, b3);
            }
        }
    }

    // Stage epilogue data (a_out rows, token ids, bias cols)
    __syncthreads();
    {
        const float4* src = (const float4*)(g_aout + (size_t)(bm * BM) * RANK);
        float4* dst = (float4*)&aS[0][0];
        for (int i = t; i < BM * RANK / 4; i += 256) dst[i] = src[i];
        if (t < BM) {
            eS[t]    = tok[bm * BM + t];
            biasS[t] = bias[bn * BN + t];
        }
    }
    __syncthreads();

#pragma unroll
    for (int i = 0; i < 8; ++i) {
        const int r = ty * 4 + (i & 3) + (i >> 2) * 64;
        const int e = eS[r];
        const float4 A0 = *(const float4*)&aS[r][0];
        const float4 A1 = *(const float4*)&aS[r][4];
        const float4 A2 = *(const float4*)&aS[r][8];
        const float4 A3 = *(const float4*)&aS[r][12];
        const float* Bp = Bbuf + ((size_t)e * D_OUT + bn * BN) * RANK;
        float* outp = out + (size_t)(bm * BM + r) * D_OUT + bn * BN;

        float vals[8];
        float2 f;
        f = unpack2(acc2[i][0]); vals[0] = f.x; vals[1] = f.y;
        f = unpack2(acc2[i][1]); vals[2] = f.x; vals[3] = f.y;
        f = unpack2(acc2[i][2]); vals[4] = f.x; vals[5] = f.y;
        f = unpack2(acc2[i][3]); vals[6] = f.x; vals[7] = f.y;

#pragma unroll
        for (int j = 0; j < 8; ++j) {
            const int c = tx * 4 + (j & 3) + (j >> 2) * 64;
            const float4* bv4 = (const float4*)(Bp + (size_t)c * RANK);
            const float4 B0 = bv4[0], B1 = bv4[1], B2 = bv4[2], B3 = bv4[3];
            const float d =
                  A0.x * B0.x + A0.y * B0.y + A0.z * B0.z + A0.w * B0.w
                + A1.x * B1.x + A1.y * B1.y + A1.z * B1.z + A1.w * B1.w
                + A2.x * B2.x + A2.y * B2.y + A2.z * B2.z + A2.w * B2.w
                + A3.x * B3.x + A3.y * B3.y + A3.z * B3.z + A3.w * B3.w;
            vals[j] += biasS[c] + d;
        }
        const float4 o0 = {vals[0], vals[1], vals[2], vals[3]};
        const float4 o1 = {vals[4], vals[5], vals[6], vals[7]};
        *(float4*)(outp + tx * 4)      = o0;
        *(float4*)(outp + tx * 4 + 64) = o1;
    }
}

// ---------------------------------------------------------------------------
extern "C" void kernel_launch(void* const* d_in, const int* in_sizes, int n_in,
                              void* d_out, int out_size)
{
    const float* x    = (const float*)d_in[0];
    const float* W    = (const float*)d_in[1];
    const float* bias = (const float*)d_in[2];
    const float* A    = (const float*)d_in[3];
    const float* B    = (const float*)d_in[4];
    const float* scal = (const float*)d_in[5];
    const int*   tok  = (const int*)d_in[6];
    float* out = (float*)d_out;

    lora_a_kernel<<<SEQ, 128>>>(x, A, scal, tok);
    fused_gemm_kernel<<<dim3(D_OUT / BN, SEQ / BM), 256>>>(x, W, bias, B, tok, out);
}

// round 9
// speedup vs baseline: 1.6792x; 1.6792x over previous
#include <cuda_runtime.h>
#include <cuda_bf16.h>
#include <cstdint>

#define SEQ    8192
#define D_IN   4096
#define D_OUT  4096
#define RANK   16
#define NADP   8

// ---- tile config -----------------------------------------------------------
#define BM 128
#define BN 128
#define BK 32                        // bf16 elements per k-chunk
#define NCHUNK (D_IN / BK)           // 128
#define KSTEPS 2                     // 2 x k16 per chunk

#define AB_BYTES (BM * BK * 2)       // 8192
#define OFF_AH 0
#define OFF_AL (AB_BYTES)            // 8192
#define OFF_BH (2 * AB_BYTES)        // 16384
#define OFF_BL (3 * AB_BYTES)        // 24576
#define STAGE_BYTES (4 * AB_BYTES)   // 32768
#define MAIN_BYTES  (2 * STAGE_BYTES)

// epilogue smem layout (float indices), reuses [0, ...)
#define COL_STRIDE 20
#define ADP_STRIDE 2564              // 128*20 + 4 (bank-skew pad)
#define AOUT_OFF   (NADP * ADP_STRIDE)        // 20512
#define BIAS_OFF   (AOUT_OFF + BM * RANK)     // 22560
#define TOK_OFF    (BIAS_OFF + BN)            // 22688
#define EPI_FLOATS (TOK_OFF + BM)             // 22816
#define SMEM_TOTAL (EPI_FLOATS * 4 > MAIN_BYTES ? EPI_FLOATS * 4 : MAIN_BYTES)

// ---- device scratch --------------------------------------------------------
__device__ float          g_aout[SEQ * RANK];
__device__ __nv_bfloat16  g_xhi[(size_t)SEQ * D_IN];
__device__ __nv_bfloat16  g_xlo[(size_t)SEQ * D_IN];
__device__ __nv_bfloat16  g_whi[(size_t)D_OUT * D_IN];  // transposed: [N][K]
__device__ __nv_bfloat16  g_wlo[(size_t)D_OUT * D_IN];

// ---- PTX helpers -----------------------------------------------------------
__device__ __forceinline__ uint32_t smem_u32(const void* p) {
    uint32_t a;
    asm("{ .reg .u64 t; cvta.to.shared.u64 t, %1; cvt.u32.u64 %0, t; }"
        : "=r"(a) : "l"(p));
    return a;
}
// 64B-row swizzle: chunk16 ^= (row>>1)&3  (conflict-free ldmatrix phases)
#define SWZ64(o) ((o) ^ (((o) >> 3) & 0x30))

#define CP16(dst, src) \
    asm volatile("cp.async.cg.shared.global [%0], [%1], 16;" \
                 :: "r"(dst), "l"(src))
#define CP_COMMIT() asm volatile("cp.async.commit_group;" ::: "memory")
#define CP_WAIT1()  asm volatile("cp.async.wait_group 1;" ::: "memory")
#define CP_WAIT0()  asm volatile("cp.async.wait_group 0;" ::: "memory")

__device__ __forceinline__ void ldsm4(uint32_t* r, uint32_t addr) {
    asm volatile("ldmatrix.sync.aligned.m8n8.x4.shared.b16 {%0,%1,%2,%3}, [%4];"
                 : "=r"(r[0]), "=r"(r[1]), "=r"(r[2]), "=r"(r[3]) : "r"(addr));
}
__device__ __forceinline__ void mma_bf16(float* d, const uint32_t* a,
                                         const uint32_t* b) {
    asm volatile(
        "mma.sync.aligned.m16n8k16.row.col.f32.bf16.bf16.f32 "
        "{%0,%1,%2,%3}, {%4,%5,%6,%7}, {%8,%9}, {%0,%1,%2,%3};"
        : "+f"(d[0]), "+f"(d[1]), "+f"(d[2]), "+f"(d[3])
        : "r"(a[0]), "r"(a[1]), "r"(a[2]), "r"(a[3]), "r"(b[0]), "r"(b[1]));
}

// ---------------------------------------------------------------------------
// hi/lo split conversion of x (elementwise, float4)
// ---------------------------------------------------------------------------
__global__ void convert_x_kernel(const float* __restrict__ x)
{
    const int i = blockIdx.x * 256 + threadIdx.x;   // float4 index
    const float4 v = ((const float4*)x)[i];
    __nv_bfloat16 h0 = __float2bfloat16(v.x);
    __nv_bfloat16 h1 = __float2bfloat16(v.y);
    __nv_bfloat16 h2 = __float2bfloat16(v.z);
    __nv_bfloat16 h3 = __float2bfloat16(v.w);
    __nv_bfloat16 l0 = __float2bfloat16(v.x - __bfloat162float(h0));
    __nv_bfloat16 l1 = __float2bfloat16(v.y - __bfloat162float(h1));
    __nv_bfloat16 l2 = __float2bfloat16(v.z - __bfloat162float(h2));
    __nv_bfloat16 l3 = __float2bfloat16(v.w - __bfloat162float(h3));
    ((__nv_bfloat162*)g_xhi)[2 * i + 0] = __nv_bfloat162(h0, h1);
    ((__nv_bfloat162*)g_xhi)[2 * i + 1] = __nv_bfloat162(h2, h3);
    ((__nv_bfloat162*)g_xlo)[2 * i + 0] = __nv_bfloat162(l0, l1);
    ((__nv_bfloat162*)g_xlo)[2 * i + 1] = __nv_bfloat162(l2, l3);
}

// ---------------------------------------------------------------------------
// transpose + hi/lo split of W:  W[k][n] fp32 -> g_whi/g_wlo[n][k] bf16
// ---------------------------------------------------------------------------
__global__ void convert_w_kernel(const float* __restrict__ W)
{
    __shared__ float t[32][33];
    const int n0 = blockIdx.x * 32, k0 = blockIdx.y * 32;
    const int tx = threadIdx.x, ty = threadIdx.y;   // 32 x 8
#pragma unroll
    for (int i = 0; i < 32; i += 8)
        t[ty + i][tx] = W[(size_t)(k0 + ty + i) * D_OUT + n0 + tx];
    __syncthreads();
#pragma unroll
    for (int i = 0; i < 32; i += 8) {
        const float v = t[tx][ty + i];              // = W[k0+tx][n0+ty+i]
        const __nv_bfloat16 h = __float2bfloat16(v);
        const size_t o = (size_t)(n0 + ty + i) * D_IN + k0 + tx;
        g_whi[o] = h;
        g_wlo[o] = __float2bfloat16(v - __bfloat162float(h));
    }
}

// ---------------------------------------------------------------------------
// a_out = (x @ A[e]^T) * scaling   (one block per token, 128 thr)
// ---------------------------------------------------------------------------
__global__ void lora_a_kernel(const float* __restrict__ x,
                              const float* __restrict__ A,
                              const float* __restrict__ scalings,
                              const int*   __restrict__ tok)
{
    const int s = blockIdx.x;
    const int t = threadIdx.x;
    const int e = tok[s];
    const float* xr = x + (size_t)s * D_IN;
    const float* Ae = A + (size_t)e * RANK * D_IN;

    float acc[RANK];
#pragma unroll
    for (int r = 0; r < RANK; ++r) acc[r] = 0.f;

#pragma unroll
    for (int it = 0; it < D_IN / (128 * 4); ++it) {
        const int k = t * 4 + it * 512;
        const float4 xv = *(const float4*)(xr + k);
#pragma unroll
        for (int r = 0; r < RANK; ++r) {
            const float4 av = *(const float4*)(Ae + r * D_IN + k);
            acc[r] += xv.x * av.x + xv.y * av.y + xv.z * av.z + xv.w * av.w;
        }
    }
#pragma unroll
    for (int r = 0; r < RANK; ++r) {
#pragma unroll
        for (int o = 16; o > 0; o >>= 1)
            acc[r] += __shfl_xor_sync(0xffffffffu, acc[r], o);
    }
    __shared__ float red[4][RANK];
    const int warp = t >> 5, lane = t & 31;
    if (lane == 0) {
#pragma unroll
        for (int r = 0; r < RANK; ++r) red[warp][r] = acc[r];
    }
    __syncthreads();
    if (t < RANK) {
        const float v = red[0][t] + red[1][t] + red[2][t] + red[3][t];
        g_aout[s * RANK + t] = v * scalings[s];
    }
}

// ---------------------------------------------------------------------------
// Main fused HMMA GEMM:  out = xh*Wh + xh*Wl + xl*Wh + bias + aout@B[e]^T
// 128x128 tile, BK=32, 256 threads (8 warps, warp tile 32x64), dbl-buffered.
// ---------------------------------------------------------------------------
__device__ __forceinline__ void load_stage(uint32_t st, int kc, int m0, int n0,
                                           int tid)
{
    const int k0 = kc * BK;
#pragma unroll
    for (int i = tid; i < BM * 4; i += 256) {       // 512 rows-chunks
        const int row = i >> 2, c = i & 3;
        const uint32_t sw = SWZ64((uint32_t)(row * 64 + c * 16));
        const size_t ga = (size_t)(m0 + row) * D_IN + k0 + c * 8;
        const size_t gb = (size_t)(n0 + row) * D_IN + k0 + c * 8;
        CP16(st + OFF_AH + sw, (const char*)(g_xhi + ga));
        CP16(st + OFF_AL + sw, (const char*)(g_xlo + ga));
        CP16(st + OFF_BH + sw, (const char*)(g_whi + gb));
        CP16(st + OFF_BL + sw, (const char*)(g_wlo + gb));
    }
}

__global__ __launch_bounds__(256, 1)
void fused_mma_kernel(const float* __restrict__ bias,
                      const float* __restrict__ Bbuf,
                      const int*   __restrict__ tok,
                      float*       __restrict__ out)
{
    extern __shared__ __align__(1024) char smem[];
    const uint32_t sb = smem_u32(smem);
    const int tid  = threadIdx.x;
    const int lane = tid & 31;
    const int wid  = tid >> 5;
    const int wm   = wid >> 1;          // 0..3 -> m offset wm*32
    const int wn   = wid & 1;           // 0..1 -> n offset wn*64
    const int m0 = blockIdx.y * BM;
    const int n0 = blockIdx.x * BN;

    // precomputed swizzled lane offsets (ks=0); ks toggles bit 5 post-swizzle
    uint32_t aswz[2], bswz[4];
#pragma unroll
    for (int mt = 0; mt < 2; ++mt)
        aswz[mt] = SWZ64((uint32_t)((wm * 32 + mt * 16 + (lane & 15)) * 64
                                    + ((lane >> 4) & 1) * 16));
#pragma unroll
    for (int ntp = 0; ntp < 4; ++ntp)
        bswz[ntp] = SWZ64((uint32_t)((wn * 64 + ntp * 16 + ((lane >> 4) & 1) * 8
                                      + (lane & 7)) * 64
                                     + ((lane >> 3) & 1) * 16));

    float acc[2][8][4];
#pragma unroll
    for (int mt = 0; mt < 2; ++mt)
#pragma unroll
        for (int nt = 0; nt < 8; ++nt)
#pragma unroll
            for (int q = 0; q < 4; ++q) acc[mt][nt][q] = 0.f;

    load_stage(sb, 0, m0, n0, tid); CP_COMMIT();
    load_stage(sb + STAGE_BYTES, 1, m0, n0, tid); CP_COMMIT();

    for (int ci = 0; ci < NCHUNK; ++ci) {
        const uint32_t st = sb + (uint32_t)(ci & 1) * STAGE_BYTES;
        if (ci + 1 < NCHUNK) { CP_WAIT1(); } else { CP_WAIT0(); }
        __syncthreads();

#pragma unroll
        for (int ks = 0; ks < KSTEPS; ++ks) {
            const uint32_t kx = (uint32_t)ks << 5;
            uint32_t ah[2][4], al_[2][4], bh[8][2], bl[8][2];
#pragma unroll
            for (int mt = 0; mt < 2; ++mt) {
                ldsm4(ah[mt],  st + OFF_AH + (aswz[mt] ^ kx));
                ldsm4(al_[mt], st + OFF_AL + (aswz[mt] ^ kx));
            }
#pragma unroll
            for (int ntp = 0; ntp < 4; ++ntp) {
                uint32_t t4[4];
                ldsm4(t4, st + OFF_BH + (bswz[ntp] ^ kx));
                bh[2 * ntp][0] = t4[0]; bh[2 * ntp][1] = t4[1];
                bh[2 * ntp + 1][0] = t4[2]; bh[2 * ntp + 1][1] = t4[3];
                ldsm4(t4, st + OFF_BL + (bswz[ntp] ^ kx));
                bl[2 * ntp][0] = t4[0]; bl[2 * ntp][1] = t4[1];
                bl[2 * ntp + 1][0] = t4[2]; bl[2 * ntp + 1][1] = t4[3];
            }
#pragma unroll
            for (int mt = 0; mt < 2; ++mt)
#pragma unroll
                for (int nt = 0; nt < 8; ++nt) {
                    mma_bf16(acc[mt][nt], ah[mt],  bh[nt]);
                    mma_bf16(acc[mt][nt], ah[mt],  bl[nt]);
                    mma_bf16(acc[mt][nt], al_[mt], bh[nt]);
                }
        }
        __syncthreads();
        if (ci + 2 < NCHUNK) {
            load_stage(sb + (uint32_t)(ci & 1) * STAGE_BYTES, ci + 2, m0, n0, tid);
            CP_COMMIT();
        }
    }
    __syncthreads();

    // ---- epilogue: stage LoRA-B slabs / a_out / bias / tokens in smem -----
    float* sf = (float*)smem;
    int* stok = (int*)(sf + TOK_OFF);
    for (int i = tid; i < NADP * BN * 4; i += 256) {      // 4096 float4s
        const int e = i >> 9, rem = i & 511, c = rem >> 2, q = rem & 3;
        const float4 v = ((const float4*)(Bbuf + ((size_t)e * D_OUT + n0 + c) * RANK))[q];
        *(float4*)(sf + e * ADP_STRIDE + c * COL_STRIDE + q * 4) = v;
    }
    for (int i = tid; i < BM * RANK / 4; i += 256)
        ((float4*)(sf + AOUT_OFF))[i] =
            ((const float4*)(g_aout + (size_t)m0 * RANK))[i];
    for (int i = tid; i < BN / 4; i += 256)
        ((float4*)(sf + BIAS_OFF))[i] = ((const float4*)(bias + n0))[i];
    if (tid < BM) stok[tid] = tok[m0 + tid];
    __syncthreads();

    // ---- combine + store --------------------------------------------------
#pragma unroll
    for (int rr = 0; rr < 4; ++rr) {
        const int mt = rr >> 1, half = rr & 1;
        const int r = wm * 32 + mt * 16 + half * 8 + (lane >> 2);
        const int e = stok[r];
        const float* ar = sf + AOUT_OFF + r * RANK;
        const float4 a0 = *(const float4*)(ar + 0);
        const float4 a1 = *(const float4*)(ar + 4);
        const float4 a2 = *(const float4*)(ar + 8);
        const float4 a3 = *(const float4*)(ar + 12);
        const float* Be = sf + e * ADP_STRIDE;
        float* outp = out + (size_t)(m0 + r) * D_OUT + n0;
#pragma unroll
        for (int nt = 0; nt < 8; ++nt) {
            const int col0 = wn * 64 + nt * 8 + 2 * (lane & 3);
            float v2[2];
#pragma unroll
            for (int c = 0; c < 2; ++c) {
                const int col = col0 + c;
                const float* bp = Be + col * COL_STRIDE;
                const float4 b0 = *(const float4*)(bp + 0);
                const float4 b1 = *(const float4*)(bp + 4);
                const float4 b2 = *(const float4*)(bp + 8);
                const float4 b3 = *(const float4*)(bp + 12);
                float d = acc[mt][nt][half * 2 + c] + sf[BIAS_OFF + col];
                d += a0.x * b0.x + a0.y * b0.y + a0.z * b0.z + a0.w * b0.w;
                d += a1.x * b1.x + a1.y * b1.y + a1.z * b1.z + a1.w * b1.w;
                d += a2.x * b2.x + a2.y * b2.y + a2.z * b2.z + a2.w * b2.w;
                d += a3.x * b3.x + a3.y * b3.y + a3.z * b3.z + a3.w * b3.w;
                v2[c] = d;
            }
            *(float2*)(outp + col0) = make_float2(v2[0], v2[1]);
        }
    }
}

// ---------------------------------------------------------------------------
extern "C" void kernel_launch(void* const* d_in, const int* in_sizes, int n_in,
                              void* d_out, int out_size)
{
    const float* x    = (const float*)d_in[0];
    const float* W    = (const float*)d_in[1];
    const float* bias = (const float*)d_in[2];
    const float* A    = (const float*)d_in[3];
    const float* B    = (const float*)d_in[4];
    const float* scal = (const float*)d_in[5];
    const int*   tok  = (const int*)d_in[6];
    float* out = (float*)d_out;

    static int smem_set = 0;
    if (!smem_set) {
        cudaFuncSetAttribute(fused_mma_kernel,
                             cudaFuncAttributeMaxDynamicSharedMemorySize,
                             SMEM_TOTAL);
        smem_set = 1;
    }

    convert_x_kernel<<<(SEQ * D_IN / 4) / 256, 256>>>(x);
    convert_w_kernel<<<dim3(D_OUT / 32, D_IN / 32), dim3(32, 8)>>>(W);
    lora_a_kernel<<<SEQ, 128>>>(x, A, scal, tok);
    fused_mma_kernel<<<dim3(D_OUT / BN, SEQ / BM), 256, SMEM_TOTAL>>>(bias, B, tok, out);
}

// round 11
// speedup vs baseline: 2.5918x; 1.5434x over previous
#include <cuda_runtime.h>
#include <cuda_bf16.h>
#include <cstdint>

#define SEQ    8192
#define D_IN   4096
#define D_OUT  4096
#define RANK   16
#define NADP   8

// ---- tile config -----------------------------------------------------------
#define BM 128
#define BN 128
#define BK 32                        // bf16 elements per k-chunk
#define NCHUNK (D_IN / BK)           // 128
#define KSTEPS 2                     // 2 x k16 per chunk
#define STAGES 4

#define AB_BYTES (BM * BK * 2)       // 8192
#define OFF_AH 0
#define OFF_AL (AB_BYTES)            // 8192
#define OFF_BH (2 * AB_BYTES)        // 16384
#define OFF_BL (3 * AB_BYTES)        // 24576
#define STAGE_BYTES (4 * AB_BYTES)   // 32768
#define MAIN_BYTES  (STAGES * STAGE_BYTES)   // 131072

// epilogue smem region (float indices), lives AFTER the pipeline stages
#define COL_STRIDE 20
#define ADP_STRIDE 2564              // 128*20 + 4 (bank-skew pad)
#define AOUT_OFF   (NADP * ADP_STRIDE)        // 20512
#define BIAS_OFF   (AOUT_OFF + BM * RANK)     // 22560
#define TOK_OFF    (BIAS_OFF + BN)            // 22688
#define EPI_FLOATS (TOK_OFF + BM)             // 22816
#define SMEM_TOTAL (MAIN_BYTES + EPI_FLOATS * 4)   // 222336

// ---- device scratch --------------------------------------------------------
__device__ float          g_aout[SEQ * RANK];
__device__ __nv_bfloat16  g_xhi[(size_t)SEQ * D_IN];
__device__ __nv_bfloat16  g_xlo[(size_t)SEQ * D_IN];
__device__ __nv_bfloat16  g_whi[(size_t)D_OUT * D_IN];  // transposed: [N][K]
__device__ __nv_bfloat16  g_wlo[(size_t)D_OUT * D_IN];

// ---- PTX helpers -----------------------------------------------------------
__device__ __forceinline__ uint32_t smem_u32(const void* p) {
    uint32_t a;
    asm("{ .reg .u64 t; cvta.to.shared.u64 t, %1; cvt.u32.u64 %0, t; }"
        : "=r"(a) : "l"(p));
    return a;
}
// 64B-row swizzle: chunk16 ^= (row>>1)&3  (conflict-free ldmatrix phases)
#define SWZ64(o) ((o) ^ (((o) >> 3) & 0x30))

#define CP16(dst, src) \
    asm volatile("cp.async.cg.shared.global [%0], [%1], 16;" \
                 :: "r"(dst), "l"(src))
#define CP_COMMIT() asm volatile("cp.async.commit_group;" ::: "memory")
#define CP_WAIT2()  asm volatile("cp.async.wait_group 2;" ::: "memory")
#define CP_WAIT1()  asm volatile("cp.async.wait_group 1;" ::: "memory")
#define CP_WAIT0()  asm volatile("cp.async.wait_group 0;" ::: "memory")

__device__ __forceinline__ void ldsm4(uint32_t* r, uint32_t addr) {
    asm volatile("ldmatrix.sync.aligned.m8n8.x4.shared.b16 {%0,%1,%2,%3}, [%4];"
                 : "=r"(r[0]), "=r"(r[1]), "=r"(r[2]), "=r"(r[3]) : "r"(addr));
}
__device__ __forceinline__ void mma_bf16(float* d, const uint32_t* a,
                                         const uint32_t* b) {
    asm volatile(
        "mma.sync.aligned.m16n8k16.row.col.f32.bf16.bf16.f32 "
        "{%0,%1,%2,%3}, {%4,%5,%6,%7}, {%8,%9}, {%0,%1,%2,%3};"
        : "+f"(d[0]), "+f"(d[1]), "+f"(d[2]), "+f"(d[3])
        : "r"(a[0]), "r"(a[1]), "r"(a[2]), "r"(a[3]), "r"(b[0]), "r"(b[1]));
}

// ---------------------------------------------------------------------------
// Fused: a_out = (x @ A[e]^T) * scaling  AND  x -> (xhi, xlo) bf16 split.
// One block per token row, 128 threads; x is read exactly once.
// ---------------------------------------------------------------------------
__global__ void lora_a_convert_kernel(const float* __restrict__ x,
                                      const float* __restrict__ A,
                                      const float* __restrict__ scalings,
                                      const int*   __restrict__ tok)
{
    const int s = blockIdx.x;
    const int t = threadIdx.x;
    const int e = tok[s];
    const float* xr = x + (size_t)s * D_IN;
    const float* Ae = A + (size_t)e * RANK * D_IN;

    float acc[RANK];
#pragma unroll
    for (int r = 0; r < RANK; ++r) acc[r] = 0.f;

#pragma unroll
    for (int it = 0; it < D_IN / (128 * 4); ++it) {
        const int k = t * 4 + it * 512;
        const float4 xv = *(const float4*)(xr + k);

        // hi/lo bf16 split (stores hidden under the dot-product FMAs)
        const __nv_bfloat16 h0 = __float2bfloat16(xv.x);
        const __nv_bfloat16 h1 = __float2bfloat16(xv.y);
        const __nv_bfloat16 h2 = __float2bfloat16(xv.z);
        const __nv_bfloat16 h3 = __float2bfloat16(xv.w);
        const __nv_bfloat16 l0 = __float2bfloat16(xv.x - __bfloat162float(h0));
        const __nv_bfloat16 l1 = __float2bfloat16(xv.y - __bfloat162float(h1));
        const __nv_bfloat16 l2 = __float2bfloat16(xv.z - __bfloat162float(h2));
        const __nv_bfloat16 l3 = __float2bfloat16(xv.w - __bfloat162float(h3));
        const size_t o = (size_t)s * D_IN + k;
        *(__nv_bfloat162*)(g_xhi + o)     = __nv_bfloat162(h0, h1);
        *(__nv_bfloat162*)(g_xhi + o + 2) = __nv_bfloat162(h2, h3);
        *(__nv_bfloat162*)(g_xlo + o)     = __nv_bfloat162(l0, l1);
        *(__nv_bfloat162*)(g_xlo + o + 2) = __nv_bfloat162(l2, l3);

#pragma unroll
        for (int r = 0; r < RANK; ++r) {
            const float4 av = *(const float4*)(Ae + r * D_IN + k);
            acc[r] += xv.x * av.x + xv.y * av.y + xv.z * av.z + xv.w * av.w;
        }
    }
#pragma unroll
    for (int r = 0; r < RANK; ++r) {
#pragma unroll
        for (int o = 16; o > 0; o >>= 1)
            acc[r] += __shfl_xor_sync(0xffffffffu, acc[r], o);
    }
    __shared__ float red[4][RANK];
    const int warp = t >> 5, lane = t & 31;
    if (lane == 0) {
#pragma unroll
        for (int r = 0; r < RANK; ++r) red[warp][r] = acc[r];
    }
    __syncthreads();
    if (t < RANK) {
        const float v = red[0][t] + red[1][t] + red[2][t] + red[3][t];
        g_aout[s * RANK + t] = v * scalings[s];
    }
}

// ---------------------------------------------------------------------------
// transpose + hi/lo split of W:  W[k][n] fp32 -> g_whi/g_wlo[n][k] bf16
// ---------------------------------------------------------------------------
__global__ void convert_w_kernel(const float* __restrict__ W)
{
    __shared__ float t[32][33];
    const int n0 = blockIdx.x * 32, k0 = blockIdx.y * 32;
    const int tx = threadIdx.x, ty = threadIdx.y;   // 32 x 8
#pragma unroll
    for (int i = 0; i < 32; i += 8)
        t[ty + i][tx] = W[(size_t)(k0 + ty + i) * D_OUT + n0 + tx];
    __syncthreads();
#pragma unroll
    for (int i = 0; i < 32; i += 8) {
        const float v = t[tx][ty + i];              // = W[k0+tx][n0+ty+i]
        const __nv_bfloat16 h = __float2bfloat16(v);
        const size_t o = (size_t)(n0 + ty + i) * D_IN + k0 + tx;
        g_whi[o] = h;
        g_wlo[o] = __float2bfloat16(v - __bfloat162float(h));
    }
}

// ---------------------------------------------------------------------------
// Main fused HMMA GEMM:  out = xh*Wh + xh*Wl + xl*Wh + bias + aout@B[e]^T
// 128x128 tile, BK=32, 256 threads (8 warps, warp tile 32x64),
// 4-stage cp.async pipeline, ONE __syncthreads per chunk.
// ---------------------------------------------------------------------------
__device__ __forceinline__ void load_stage(uint32_t st, int kc, int m0, int n0,
                                           int tid)
{
    const int k0 = kc * BK;
#pragma unroll
    for (int i = tid; i < BM * 4; i += 256) {       // 512 row-chunks
        const int row = i >> 2, c = i & 3;
        const uint32_t sw = SWZ64((uint32_t)(row * 64 + c * 16));
        const size_t ga = (size_t)(m0 + row) * D_IN + k0 + c * 8;
        const size_t gb = (size_t)(n0 + row) * D_IN + k0 + c * 8;
        CP16(st + OFF_AH + sw, (const char*)(g_xhi + ga));
        CP16(st + OFF_AL + sw, (const char*)(g_xlo + ga));
        CP16(st + OFF_BH + sw, (const char*)(g_whi + gb));
        CP16(st + OFF_BL + sw, (const char*)(g_wlo + gb));
    }
}

__global__ __launch_bounds__(256, 1)
void fused_mma_kernel(const float* __restrict__ bias,
                      const float* __restrict__ Bbuf,
                      const int*   __restrict__ tok,
                      float*       __restrict__ out)
{
    extern __shared__ __align__(1024) char smem[];
    const uint32_t sb = smem_u32(smem);
    const int tid  = threadIdx.x;
    const int lane = tid & 31;
    const int wid  = tid >> 5;
    const int wm   = wid >> 1;          // 0..3 -> m offset wm*32
    const int wn   = wid & 1;           // 0..1 -> n offset wn*64
    const int m0 = blockIdx.y * BM;
    const int n0 = blockIdx.x * BN;

    // precomputed swizzled lane offsets (ks=0); ks toggles bit 5 post-swizzle
    uint32_t aswz[2], bswz[4];
#pragma unroll
    for (int mt = 0; mt < 2; ++mt)
        aswz[mt] = SWZ64((uint32_t)((wm * 32 + mt * 16 + (lane & 15)) * 64
                                    + ((lane >> 4) & 1) * 16));
#pragma unroll
    for (int ntp = 0; ntp < 4; ++ntp)
        bswz[ntp] = SWZ64((uint32_t)((wn * 64 + ntp * 16 + ((lane >> 4) & 1) * 8
                                      + (lane & 7)) * 64
                                     + ((lane >> 3) & 1) * 16));

    float acc[2][8][4];
#pragma unroll
    for (int mt = 0; mt < 2; ++mt)
#pragma unroll
        for (int nt = 0; nt < 8; ++nt)
#pragma unroll
            for (int q = 0; q < 4; ++q) acc[mt][nt][q] = 0.f;

    // prologue: fill stages 0..2
    load_stage(sb + 0 * STAGE_BYTES, 0, m0, n0, tid); CP_COMMIT();
    load_stage(sb + 1 * STAGE_BYTES, 1, m0, n0, tid); CP_COMMIT();
    load_stage(sb + 2 * STAGE_BYTES, 2, m0, n0, tid); CP_COMMIT();

    // stage epilogue data into its DEDICATED region (overlapped with pipeline)
    float* ef = (float*)(smem + MAIN_BYTES);
    int* stok = (int*)(ef + TOK_OFF);
    for (int i = tid; i < NADP * BN * 4; i += 256) {      // 4096 float4s
        const int e = i >> 9, rem = i & 511, c = rem >> 2, q = rem & 3;
        const float4 v = ((const float4*)(Bbuf + ((size_t)e * D_OUT + n0 + c) * RANK))[q];
        *(float4*)(ef + e * ADP_STRIDE + c * COL_STRIDE + q * 4) = v;
    }
    for (int i = tid; i < BM * RANK / 4; i += 256)
        ((float4*)(ef + AOUT_OFF))[i] =
            ((const float4*)(g_aout + (size_t)m0 * RANK))[i];
    for (int i = tid; i < BN / 4; i += 256)
        ((float4*)(ef + BIAS_OFF))[i] = ((const float4*)(bias + n0))[i];
    if (tid < BM) stok[tid] = tok[m0 + tid];

    for (int ci = 0; ci < NCHUNK; ++ci) {
        // retire the group for chunk ci
        if (ci <= NCHUNK - 3)      { CP_WAIT2(); }
        else if (ci == NCHUNK - 2) { CP_WAIT1(); }
        else                       { CP_WAIT0(); }
        __syncthreads();   // data(ci) visible; buffer (ci-1)%4 fully consumed

        // refill the freed buffer with chunk ci+3
        if (ci + 3 < NCHUNK) {
            load_stage(sb + (uint32_t)((ci + 3) & 3) * STAGE_BYTES,
                       ci + 3, m0, n0, tid);
            CP_COMMIT();
        }

        const uint32_t st = sb + (uint32_t)(ci & 3) * STAGE_BYTES;
#pragma unroll
        for (int ks = 0; ks < KSTEPS; ++ks) {
            const uint32_t kx = (uint32_t)ks << 5;
            uint32_t ah[2][4], al_[2][4], bh[8][2], bl[8][2];
#pragma unroll
            for (int mt = 0; mt < 2; ++mt) {
                ldsm4(ah[mt],  st + OFF_AH + (aswz[mt] ^ kx));
                ldsm4(al_[mt], st + OFF_AL + (aswz[mt] ^ kx));
            }
#pragma unroll
            for (int ntp = 0; ntp < 4; ++ntp) {
                uint32_t t4[4];
                ldsm4(t4, st + OFF_BH + (bswz[ntp] ^ kx));
                bh[2 * ntp][0] = t4[0]; bh[2 * ntp][1] = t4[1];
                bh[2 * ntp + 1][0] = t4[2]; bh[2 * ntp + 1][1] = t4[3];
                ldsm4(t4, st + OFF_BL + (bswz[ntp] ^ kx));
                bl[2 * ntp][0] = t4[0]; bl[2 * ntp][1] = t4[1];
                bl[2 * ntp + 1][0] = t4[2]; bl[2 * ntp + 1][1] = t4[3];
            }
#pragma unroll
            for (int mt = 0; mt < 2; ++mt)
#pragma unroll
                for (int nt = 0; nt < 8; ++nt) {
                    mma_bf16(acc[mt][nt], ah[mt],  bh[nt]);
                    mma_bf16(acc[mt][nt], ah[mt],  bl[nt]);
                    mma_bf16(acc[mt][nt], al_[mt], bh[nt]);
                }
        }
    }

    // ---- combine + store (epi region already staged; visible via loop syncs)
#pragma unroll
    for (int rr = 0; rr < 4; ++rr) {
        const int mt = rr >> 1, half = rr & 1;
        const int r = wm * 32 + mt * 16 + half * 8 + (lane >> 2);
        const int e = stok[r];
        const float* ar = ef + AOUT_OFF + r * RANK;
        const float4 a0 = *(const float4*)(ar + 0);
        const float4 a1 = *(const float4*)(ar + 4);
        const float4 a2 = *(const float4*)(ar + 8);
        const float4 a3 = *(const float4*)(ar + 12);
        const float* Be = ef + e * ADP_STRIDE;
        float* outp = out + (size_t)(m0 + r) * D_OUT + n0;
#pragma unroll
        for (int nt = 0; nt < 8; ++nt) {
            const int col0 = wn * 64 + nt * 8 + 2 * (lane & 3);
            float v2[2];
#pragma unroll
            for (int c = 0; c < 2; ++c) {
                const int col = col0 + c;
                const float* bp = Be + col * COL_STRIDE;
                const float4 b0 = *(const float4*)(bp + 0);
                const float4 b1 = *(const float4*)(bp + 4);
                const float4 b2 = *(const float4*)(bp + 8);
                const float4 b3 = *(const float4*)(bp + 12);
                float d = acc[mt][nt][half * 2 + c] + ef[BIAS_OFF + col];
                d += a0.x * b0.x + a0.y * b0.y + a0.z * b0.z + a0.w * b0.w;
                d += a1.x * b1.x + a1.y * b1.y + a1.z * b1.z + a1.w * b1.w;
                d += a2.x * b2.x + a2.y * b2.y + a2.z * b2.z + a2.w * b2.w;
                d += a3.x * b3.x + a3.y * b3.y + a3.z * b3.z + a3.w * b3.w;
                v2[c] = d;
            }
            *(float2*)(outp + col0) = make_float2(v2[0], v2[1]);
        }
    }
}

// ---------------------------------------------------------------------------
extern "C" void kernel_launch(void* const* d_in, const int* in_sizes, int n_in,
                              void* d_out, int out_size)
{
    const float* x    = (const float*)d_in[0];
    const float* W    = (const float*)d_in[1];
    const float* bias = (const float*)d_in[2];
    const float* A    = (const float*)d_in[3];
    const float* B    = (const float*)d_in[4];
    const float* scal = (const float*)d_in[5];
    const int*   tok  = (const int*)d_in[6];
    float* out = (float*)d_out;

    static int smem_set = 0;
    if (!smem_set) {
        cudaFuncSetAttribute(fused_mma_kernel,
                             cudaFuncAttributeMaxDynamicSharedMemorySize,
                             SMEM_TOTAL);
        smem_set = 1;
    }

    convert_w_kernel<<<dim3(D_OUT / 32, D_IN / 32), dim3(32, 8)>>>(W);
    lora_a_convert_kernel<<<SEQ, 128>>>(x, A, scal, tok);
    fused_mma_kernel<<<dim3(D_OUT / BN, SEQ / BM), 256, SMEM_TOTAL>>>(bias, B, tok, out);
}